// round 5
// baseline (speedup 1.0000x reference)
#include <cuda_runtime.h>
#include <math.h>
#include <stdint.h>

#define BB 256
#define HH 512
#define H4 2048
#define LEN 48
#define LOOKN 10
#define K2H 1024
#define STARTI 48
#define LABW 58
#define NBLK 256
#define NTHR 128

// ---- scratch layout (floats; tf32 u32 data stored in float slots) ----
constexpr size_t O_WISEQ = 0;
constexpr size_t O_MID2  = O_WISEQ + (size_t)BB*LEN*HH;
constexpr size_t O_Y     = O_MID2  + (size_t)BB*LEN*HH;
constexpr size_t O_HT0   = O_Y     + (size_t)BB*LEN*HH;
constexpr size_t O_HT1   = O_HT0   + (size_t)BB*K2H;
constexpr size_t O_HE0   = O_HT1   + (size_t)BB*K2H;
constexpr size_t O_HE1   = O_HE0   + (size_t)BB*K2H;
constexpr size_t O_HM0   = O_HE1   + (size_t)BB*K2H;
constexpr size_t O_HM1   = O_HM0   + (size_t)BB*K2H;
constexpr size_t O_DECIN = O_HM1   + (size_t)BB*K2H;
constexpr size_t O_WTWHO = O_DECIN + (size_t)BB*HH;
constexpr size_t O_TU    = O_WTWHO + (size_t)BB*K2H;
constexpr size_t O_SC    = O_TU    + (size_t)BB*HH;
constexpr size_t O_XM    = O_SC    + (size_t)BB*HH;
constexpr size_t O_LAB   = O_XM    + (size_t)BB*HH;
constexpr size_t O_BSPI  = O_LAB   + 1024;
constexpr size_t O_BTGI  = O_BSPI  + H4;
constexpr size_t O_BMDI  = O_BTGI  + H4;
constexpr size_t O_WTGCI = O_BMDI  + H4;
constexpr size_t O_WI32  = O_WTGCI + H4;
constexpr size_t O_WE32  = O_WI32  + (size_t)512*512;
constexpr size_t O_VD32  = O_WE32  + (size_t)512*1024;
constexpr size_t O_WX32  = O_VD32  + (size_t)512*512;
constexpr size_t O_WTWH32= O_WX32  + (size_t)512*512;
constexpr size_t O_SPIH  = O_WTWH32+ (size_t)1024*1024;
constexpr size_t O_SPHH  = O_SPIH  + (size_t)H4*512;
constexpr size_t O_TGX   = O_SPHH  + (size_t)H4*512;
constexpr size_t O_TGHH  = O_TGX   + (size_t)H4*512;
constexpr size_t O_MDIH  = O_TGHH  + (size_t)H4*512;
constexpr size_t O_MDHH  = O_MDIH  + (size_t)H4*512;
constexpr size_t G_TOTAL = O_MDHH  + (size_t)H4*512;

__device__ float g_buf[G_TOTAL];
__device__ unsigned g_arrive;
__device__ unsigned g_release;

__device__ __forceinline__ void gsync(unsigned ph)
{
    __syncthreads();
    if (threadIdx.x == 0) {
        __threadfence();
        unsigned arrived = atomicAdd(&g_arrive, 1u) + 1u;
        if (arrived == (unsigned)NBLK * ph) {
            atomicExch(&g_release, ph);
        } else {
            while (*(volatile unsigned*)&g_release < ph) { __nanosleep(64); }
        }
        __threadfence();
    }
    __syncthreads();
}

__device__ __forceinline__ uint32_t f2tf32(float x)
{
    uint32_t u;
    asm("cvt.rna.tf32.f32 %0, %1;" : "=r"(u) : "f"(x));
    return u;
}

__device__ __forceinline__ void mma_tf32(float* d,
    uint32_t a0, uint32_t a1, uint32_t a2, uint32_t a3,
    uint32_t b0, uint32_t b1)
{
    asm volatile(
        "mma.sync.aligned.m16n8k8.row.col.f32.tf32.tf32.f32 "
        "{%0,%1,%2,%3},{%4,%5,%6,%7},{%8,%9},{%0,%1,%2,%3};"
        : "+f"(d[0]), "+f"(d[1]), "+f"(d[2]), "+f"(d[3])
        : "r"(a0), "r"(a1), "r"(a2), "r"(a3), "r"(b0), "r"(b1));
}

struct Params {
    const float *inp;
    const float *Wi_b, *Vd_b, *Wx_b, *V_w, *V_b, *reg_w, *reg_b;
    float* out;
    float* gb;
};

// ---- tf32 tensor-core GEMM, block tile 32x64, warp grid 2x2 (warp tile 16x32) ----
// C = act( A1@W1^T + A2@W2^T + bias + add1 + add2 + r1u[m]*r1v[n] )
// mode 0 = store, 1 = tanh+store, 2 = fused LSTM (interleaved gates h*4+g):
//   reads old c from cin, writes h/c into outp (stride 1024), optional hout.
__device__ void gemm_mma(
    const float* __restrict__ A1, int lda1, const uint32_t* __restrict__ W1, int K1,
    const float* __restrict__ A2, int lda2, const uint32_t* __restrict__ W2, int K2,
    const float* __restrict__ bias,
    const float* __restrict__ add1, int ld1,
    const float* __restrict__ add2, int ld2,
    const float* __restrict__ r1u, const float* __restrict__ r1v,
    const float* __restrict__ cin,
    float* __restrict__ outp, int M, int N, int mode,
    float* __restrict__ hout, int hstride,
    uint32_t (*sA)[20], uint32_t (*sW)[20],
    int vbid, int vgrid)
{
    const int tid = threadIdx.x;
    const int wid = tid >> 5, lane = tid & 31;
    const int g = lane >> 2, tg = lane & 3;
    const int wm = (wid >> 1) << 4, wn = (wid & 1) << 5;
    const int am = tid >> 2, aq = (tid & 3) << 2;
    const int ws = tid >> 1, wq = (tid & 1) << 3;
    const int nct = N >> 6;
    const int ntiles = (M >> 5) * nct;

    for (int t = vbid; t < ntiles; t += vgrid) {
        const int m0 = (t / nct) << 5, n0 = (t % nct) << 6;
        float acc[4][4];
#pragma unroll
        for (int j = 0; j < 4; j++)
#pragma unroll
            for (int i = 0; i < 4; i++) acc[j][i] = 0.f;

        for (int seg = 0; seg < 2; ++seg) {
            const float* A = seg ? A2 : A1;
            if (!A) continue;
            const uint32_t* W = seg ? W2 : W1;
            const int lda = seg ? lda2 : lda1;
            const int K   = seg ? K2   : K1;

            float4 pa  = *(const float4*)(A + (size_t)(m0 + am) * lda + aq);
            uint4  pw0 = *(const uint4*)(W + (size_t)(n0 + ws) * K + wq);
            uint4  pw1 = *(const uint4*)(W + (size_t)(n0 + ws) * K + wq + 4);

            for (int k0 = 0; k0 < K; k0 += 16) {
                __syncthreads();
                sA[am][aq+0] = f2tf32(pa.x);
                sA[am][aq+1] = f2tf32(pa.y);
                sA[am][aq+2] = f2tf32(pa.z);
                sA[am][aq+3] = f2tf32(pa.w);
                *(uint4*)&sW[ws][wq]   = pw0;
                *(uint4*)&sW[ws][wq+4] = pw1;
                __syncthreads();
                const int kn = k0 + 16;
                if (kn < K) {
                    pa  = *(const float4*)(A + (size_t)(m0 + am) * lda + kn + aq);
                    pw0 = *(const uint4*)(W + (size_t)(n0 + ws) * K + kn + wq);
                    pw1 = *(const uint4*)(W + (size_t)(n0 + ws) * K + kn + wq + 4);
                }
                const uint32_t a0 = sA[wm+g][tg],    a1 = sA[wm+g+8][tg];
                const uint32_t a2 = sA[wm+g][tg+4],  a3 = sA[wm+g+8][tg+4];
                const uint32_t a4 = sA[wm+g][8+tg],  a5 = sA[wm+g+8][8+tg];
                const uint32_t a6 = sA[wm+g][12+tg], a7 = sA[wm+g+8][12+tg];
#pragma unroll
                for (int j = 0; j < 4; ++j) {
                    const int nr = wn + 8*j + g;
                    mma_tf32(acc[j], a0, a1, a2, a3, sW[nr][tg],   sW[nr][tg+4]);
                    mma_tf32(acc[j], a4, a5, a6, a7, sW[nr][8+tg], sW[nr][12+tg]);
                }
            }
        }

        const int mA = m0 + wm + g, mB = mA + 8;
        if (mode < 2) {
#pragma unroll
            for (int j = 0; j < 4; ++j) {
                const int nc0 = n0 + wn + 8*j + 2*tg, nc1 = nc0 + 1;
                float v00 = acc[j][0], v01 = acc[j][1];
                float v10 = acc[j][2], v11 = acc[j][3];
                if (bias) { v00 += bias[nc0]; v01 += bias[nc1];
                            v10 += bias[nc0]; v11 += bias[nc1]; }
                if (add1) { v00 += add1[(size_t)mA*ld1+nc0]; v01 += add1[(size_t)mA*ld1+nc1];
                            v10 += add1[(size_t)mB*ld1+nc0]; v11 += add1[(size_t)mB*ld1+nc1]; }
                if (add2) { v00 += add2[(size_t)mA*ld2+nc0]; v01 += add2[(size_t)mA*ld2+nc1];
                            v10 += add2[(size_t)mB*ld2+nc0]; v11 += add2[(size_t)mB*ld2+nc1]; }
                if (mode == 1) {
                    v00 = tanhf(v00); v01 = tanhf(v01);
                    v10 = tanhf(v10); v11 = tanhf(v11);
                }
                outp[(size_t)mA*N + nc0] = v00; outp[(size_t)mA*N + nc1] = v01;
                outp[(size_t)mB*N + nc0] = v10; outp[(size_t)mB*N + nc1] = v11;
            }
        } else {
#pragma unroll
            for (int j = 0; j < 4; ++j) {
                const int nb = n0 + wn + 8*j;
                const int nc0 = nb + 2*tg, nc1 = nc0 + 1;
                float v00 = acc[j][0] + bias[nc0], v01 = acc[j][1] + bias[nc1];
                float v10 = acc[j][2] + bias[nc0], v11 = acc[j][3] + bias[nc1];
                if (r1u) {
                    const float ra = r1u[mA], rb = r1u[mB];
                    v00 += ra * r1v[nc0]; v01 += ra * r1v[nc1];
                    v10 += rb * r1v[nc0]; v11 += rb * r1v[nc1];
                }
                const float t00 = __shfl_xor_sync(0xffffffffu, v00, 1);
                const float t01 = __shfl_xor_sync(0xffffffffu, v01, 1);
                const float t10 = __shfl_xor_sync(0xffffffffu, v10, 1);
                const float t11 = __shfl_xor_sync(0xffffffffu, v11, 1);
                int m; float fi, ff, fg, fo;
                if ((tg & 1) == 0) { m = mA; fi = v00; ff = v01; fg = t00; fo = t01; }
                else               { m = mB; fi = t10; ff = t11; fg = v10; fo = v11; }
                const int h = (nb >> 2) + (tg >> 1);
                const float cold = cin[(size_t)m*1024 + 512 + h];
                const float si = 1.f / (1.f + expf(-fi));
                const float sf = 1.f / (1.f + expf(-ff));
                const float so = 1.f / (1.f + expf(-fo));
                const float c2 = sf * cold + si * tanhf(fg);
                const float hn = so * tanhf(c2);
                outp[(size_t)m*1024 + h]       = hn;
                outp[(size_t)m*1024 + 512 + h] = c2;
                if (hout) hout[(size_t)m*hstride + h] = hn;
            }
        }
        __syncthreads();
    }
}

__device__ void softmax_dev(const float* __restrict__ sc, const float* __restrict__ x,
                            int t, float* __restrict__ xm, float* red)
{
    const int b = blockIdx.x, tid = threadIdx.x;
    const int lane = tid & 31, wid = tid >> 5;
    const float* sr = sc + (size_t)b * 512;
    float v0 = sr[tid], v1 = sr[tid+128], v2 = sr[tid+256], v3 = sr[tid+384];
    float m = fmaxf(fmaxf(v0, v1), fmaxf(v2, v3));
#pragma unroll
    for (int o = 16; o; o >>= 1) m = fmaxf(m, __shfl_xor_sync(0xffffffffu, m, o));
    if (lane == 0) red[wid] = m;
    __syncthreads();
    const float bm = fmaxf(fmaxf(red[0], red[1]), fmaxf(red[2], red[3]));
    __syncthreads();
    const float e0 = expf(v0-bm), e1 = expf(v1-bm), e2 = expf(v2-bm), e3 = expf(v3-bm);
    float s = e0 + e1 + e2 + e3;
#pragma unroll
    for (int o = 16; o; o >>= 1) s += __shfl_xor_sync(0xffffffffu, s, o);
    if (lane == 0) red[wid] = s;
    __syncthreads();
    const float inv = 1.f / (red[0] + red[1] + red[2] + red[3]);
    const float* xr = x + ((size_t)b * LEN + t) * 512;
    xm[(size_t)b*512 + tid]     = xr[tid]     * e0 * inv;
    xm[(size_t)b*512 + tid+128] = xr[tid+128] * e1 * inv;
    xm[(size_t)b*512 + tid+256] = xr[tid+256] * e2 * inv;
    xm[(size_t)b*512 + tid+384] = xr[tid+384] * e3 * inv;
    __syncthreads();
}

__device__ void dec_dev(const float* __restrict__ y, const float* __restrict__ wh,
                        const float* __restrict__ Vw, const float* __restrict__ Vb,
                        const float* __restrict__ mid2, float* __restrict__ decin,
                        float* ssc)
{
    const int b = blockIdx.x, tid = threadIdx.x;
    const int lane = tid & 31, wid = tid >> 5;
    for (int l = wid; l < LEN; l += 4) {
        const float* yr = y + ((size_t)b * LEN + l) * HH;
        float pv = 0.f;
        for (int h = lane; h < HH; h += 32)
            pv += tanhf(wh[(size_t)b * K2H + h] + yr[h]) * Vw[h];
#pragma unroll
        for (int o = 16; o; o >>= 1) pv += __shfl_xor_sync(0xffffffffu, pv, o);
        if (lane == 0) ssc[l] = pv + Vb[0];
    }
    __syncthreads();
    float a0 = 0.f, a1 = 0.f, a2 = 0.f, a3 = 0.f;
    for (int l = 0; l < LEN; l++) {
        const float s = ssc[l];
        const float* mr = mid2 + ((size_t)b * LEN + l) * HH;
        a0 += s * mr[tid];     a1 += s * mr[tid+128];
        a2 += s * mr[tid+256]; a3 += s * mr[tid+384];
    }
    decin[(size_t)b*HH + tid]     = a0;
    decin[(size_t)b*HH + tid+128] = a1;
    decin[(size_t)b*HH + tid+256] = a2;
    decin[(size_t)b*HH + tid+384] = a3;
    __syncthreads();
}

// ---- persistent mega kernel ----
__global__ __launch_bounds__(NTHR) void mega(Params p)
{
    __shared__ uint32_t sA[32][20];
    __shared__ uint32_t sW[64][20];
    __shared__ float red[4];
    __shared__ float ssc[LEN];

    float* gb    = p.gb;
    float* wiseq = gb + O_WISEQ;  float* mid2  = gb + O_MID2;
    float* ybuf  = gb + O_Y;
    float* ht0   = gb + O_HT0;    float* ht1   = gb + O_HT1;
    float* he0   = gb + O_HE0;    float* he1   = gb + O_HE1;
    float* hm0   = gb + O_HM0;    float* hm1   = gb + O_HM1;
    float* decin = gb + O_DECIN;  float* wtwho = gb + O_WTWHO;
    float* tu    = gb + O_TU;     float* sc    = gb + O_SC;
    float* xm    = gb + O_XM;     float* lab   = gb + O_LAB;
    float* bspi  = gb + O_BSPI;   float* btgi  = gb + O_BTGI;
    float* bmdi  = gb + O_BMDI;   float* wtgci = gb + O_WTGCI;
    const uint32_t* WI32   = (const uint32_t*)(gb + O_WI32);
    const uint32_t* WE32   = (const uint32_t*)(gb + O_WE32);
    const uint32_t* VD32   = (const uint32_t*)(gb + O_VD32);
    const uint32_t* WX32   = (const uint32_t*)(gb + O_WX32);
    const uint32_t* WTWH32 = (const uint32_t*)(gb + O_WTWH32);
    const uint32_t* SPIH   = (const uint32_t*)(gb + O_SPIH);
    const uint32_t* SPHH   = (const uint32_t*)(gb + O_SPHH);
    const uint32_t* TGX    = (const uint32_t*)(gb + O_TGX);
    const uint32_t* TGHH   = (const uint32_t*)(gb + O_TGHH);
    const uint32_t* MDIH   = (const uint32_t*)(gb + O_MDIH);
    const uint32_t* MDHH   = (const uint32_t*)(gb + O_MDHH);

    unsigned ph = 0;

    // wiseq = input @ Wi^T + Wi_b
    gemm_mma(p.inp, 512, WI32, 512, nullptr, 0, nullptr, 0,
             p.Wi_b, nullptr, 0, nullptr, 0, nullptr, nullptr, nullptr,
             wiseq, BB*LEN, HH, 0, nullptr, 0, sA, sW, blockIdx.x, NBLK);
    gsync(++ph);

    for (int k = 0; k < LOOKN; k++) {
        float* htin  = (k & 1) ? ht1 : ht0;
        float* htout = (k & 1) ? ht0 : ht1;

        // tg gates (fused LSTM): decin@TGX^T + htin@TGHH^T + b + lab*wtgc
        gemm_mma(decin, 512, TGX, 512, htin, K2H, TGHH, 512,
                 btgi, nullptr, 0, nullptr, 0, lab, wtgci, htin,
                 htout, BB, H4, 2, nullptr, 0, sA, sW, blockIdx.x, NBLK);
        gsync(++ph);

        // packed: wtwh gemm (blocks 0-127) | target (128) | zero states (129-255)
        if (blockIdx.x < 128) {
            gemm_mma(htout, K2H, WTWH32, K2H, nullptr, 0, nullptr, 0,
                     nullptr, nullptr, 0, nullptr, 0, nullptr, nullptr, nullptr,
                     wtwho, BB, K2H, 0, nullptr, 0, sA, sW, blockIdx.x, 128);
        } else if (blockIdx.x == 128) {
            const int lane = threadIdx.x & 31, wid = threadIdx.x >> 5;
            for (int r = wid; r < BB; r += 4) {
                float s = 0.f;
                for (int h = lane; h < HH; h += 32)
                    s += htout[(size_t)r * K2H + h] * p.reg_w[h];
#pragma unroll
                for (int o = 16; o; o >>= 1) s += __shfl_xor_sync(0xffffffffu, s, o);
                if (lane == 0) {
                    const float tv = s + p.reg_b[0];
                    p.out[r * LOOKN + k] = tv;
                    lab[r] = tv;
                }
            }
        } else {
            const int base = (blockIdx.x - 129) * NTHR + threadIdx.x;
            for (int i = base; i < BB * K2H; i += 127 * NTHR) {
                he0[i] = 0.f;
                hm0[i] = 0.f;
            }
        }
        gsync(++ph);

        for (int l = 0; l < LEN; l++) {
            float* hein  = (l & 1) ? he1 : he0;
            float* heout = (l & 1) ? he0 : he1;
            float* hmin  = (l & 1) ? hm1 : hm0;
            float* hmout = (l & 1) ? hm0 : hm1;

            // tu = tanh(hein@We^T + wi_x[l] + wt)
            gemm_mma(hein, K2H, WE32, K2H, nullptr, 0, nullptr, 0,
                     nullptr, wiseq + (size_t)l * HH, LEN*HH, wtwho, K2H,
                     nullptr, nullptr, nullptr,
                     tu, BB, HH, 1, nullptr, 0, sA, sW, blockIdx.x, NBLK);
            gsync(++ph);
            // sc = tu @ Vd^T + Vd_b
            gemm_mma(tu, 512, VD32, 512, nullptr, 0, nullptr, 0,
                     p.Vd_b, nullptr, 0, nullptr, 0, nullptr, nullptr, nullptr,
                     sc, BB, HH, 0, nullptr, 0, sA, sW, blockIdx.x, NBLK);
            gsync(++ph);
            softmax_dev(sc, p.inp, l, xm, red);
            gsync(++ph);
            // sp gates (fused LSTM)
            gemm_mma(xm, 512, SPIH, 512, hein, K2H, SPHH, 512,
                     bspi, nullptr, 0, nullptr, 0, nullptr, nullptr, hein,
                     heout, BB, H4, 2, nullptr, 0, sA, sW, blockIdx.x, NBLK);
            gsync(++ph);
            // mid gates (fused LSTM) + mid2 output
            gemm_mma(heout, K2H, MDIH, 512, hmin, K2H, MDHH, 512,
                     bmdi, nullptr, 0, nullptr, 0, nullptr, nullptr, hmin,
                     hmout, BB, H4, 2, mid2 + (size_t)l * HH, LEN*HH,
                     sA, sW, blockIdx.x, NBLK);
            gsync(++ph);
        }
        // y = mid2 @ Wx^T + Wx_b
        gemm_mma(mid2, 512, WX32, 512, nullptr, 0, nullptr, 0,
                 p.Wx_b, nullptr, 0, nullptr, 0, nullptr, nullptr, nullptr,
                 ybuf, BB*LEN, HH, 0, nullptr, 0, sA, sW, blockIdx.x, NBLK);
        gsync(++ph);
        dec_dev(ybuf, wtwho + 512, p.V_w, p.V_b, mid2, decin, ssc);
        gsync(++ph);
    }
}

// ---- prep: tf32 conversions, gate interleaving, bias combines ----
__global__ __launch_bounds__(256) void prep_k(
    const float* bihsp, const float* bhhsp, const float* bihtg, const float* bhhtg,
    const float* bihmid, const float* bhhmid, const float* wihtg,
    const float* wtw, const float* whw,
    const float* wisp, const float* whsp, const float* whtg,
    const float* wimd, const float* whmd,
    const float* wiw, const float* wew, const float* vdw, const float* wxw)
{
    const int nt = gridDim.x * 256;
    const int gid = blockIdx.x * 256 + threadIdx.x;
    uint32_t* WI32   = (uint32_t*)(g_buf + O_WI32);
    uint32_t* WE32   = (uint32_t*)(g_buf + O_WE32);
    uint32_t* VD32   = (uint32_t*)(g_buf + O_VD32);
    uint32_t* WX32   = (uint32_t*)(g_buf + O_WX32);
    uint32_t* WTWH32 = (uint32_t*)(g_buf + O_WTWH32);
    uint32_t* SPIH   = (uint32_t*)(g_buf + O_SPIH);
    uint32_t* SPHH   = (uint32_t*)(g_buf + O_SPHH);
    uint32_t* TGX    = (uint32_t*)(g_buf + O_TGX);
    uint32_t* TGHH   = (uint32_t*)(g_buf + O_TGHH);
    uint32_t* MDIH   = (uint32_t*)(g_buf + O_MDIH);
    uint32_t* MDHH   = (uint32_t*)(g_buf + O_MDHH);

    for (int i = gid; i < 512*512; i += nt) {
        WI32[i] = f2tf32(wiw[i]);
        VD32[i] = f2tf32(vdw[i]);
        WX32[i] = f2tf32(wxw[i]);
    }
    for (int i = gid; i < 512*1024; i += nt) WE32[i] = f2tf32(wew[i]);
    for (int i = gid; i < 1024*1024; i += nt) {
        const int r = i >> 10, c = i & 1023;
        WTWH32[i] = f2tf32(r < 512 ? wtw[(size_t)r*1024 + c]
                                   : whw[(size_t)(r-512)*1024 + c]);
    }
    for (int i = gid; i < H4*512; i += nt) {
        const int rp = i >> 9, kk = i & 511;
        const int h = rp >> 2, gg = rp & 3;
        const size_t src = (size_t)(gg * 512 + h);
        SPIH[i] = f2tf32(wisp[src*512 + kk]);
        SPHH[i] = f2tf32(whsp[src*512 + kk]);
        TGHH[i] = f2tf32(whtg[src*512 + kk]);
        MDIH[i] = f2tf32(wimd[src*512 + kk]);
        MDHH[i] = f2tf32(whmd[src*512 + kk]);
        TGX[i]  = f2tf32(wihtg[src*513 + 1 + kk]);
    }
    for (int i = gid; i < H4; i += nt) {
        const int h = i >> 2, gg = i & 3;
        const int s = gg * 512 + h;
        g_buf[O_BSPI + i]  = bihsp[s] + bhhsp[s];
        g_buf[O_BTGI + i]  = bihtg[s] + bhhtg[s];
        g_buf[O_BMDI + i]  = bihmid[s] + bhhmid[s];
        g_buf[O_WTGCI + i] = wihtg[(size_t)s * 513];
    }
}

__global__ __launch_bounds__(256) void init_k(const float* __restrict__ labp)
{
    const int i = blockIdx.x * 256 + threadIdx.x;
    if (i == 0) { g_arrive = 0u; g_release = 0u; }
    if (i < BB * K2H) g_buf[O_HT0 + i] = 0.f;
    if (i < BB * HH)  g_buf[O_DECIN + i] = 0.f;
    if (i < BB)       g_buf[O_LAB + i] = labp[(size_t)i * LABW + STARTI];
}

extern "C" void kernel_launch(void* const* d_in, const int* in_sizes, int n_in,
                              void* d_out, int out_size)
{
    Params p;
    p.inp   = (const float*)d_in[0];
    p.Wi_b  = (const float*)d_in[15];
    p.Vd_b  = (const float*)d_in[19];
    p.Wx_b  = (const float*)d_in[21];
    p.V_w   = (const float*)d_in[23];
    p.V_b   = (const float*)d_in[24];
    p.reg_w = (const float*)d_in[25];
    p.reg_b = (const float*)d_in[26];
    p.out   = (float*)d_out;

    float* gb = nullptr;
    cudaGetSymbolAddress((void**)&gb, g_buf);
    p.gb = gb;

    prep_k<<<2048, 256>>>(
        (const float*)d_in[4], (const float*)d_in[5], (const float*)d_in[8],
        (const float*)d_in[9], (const float*)d_in[12], (const float*)d_in[13],
        (const float*)d_in[6], (const float*)d_in[17], (const float*)d_in[22],
        (const float*)d_in[2], (const float*)d_in[3], (const float*)d_in[7],
        (const float*)d_in[10], (const float*)d_in[11],
        (const float*)d_in[14], (const float*)d_in[16],
        (const float*)d_in[18], (const float*)d_in[20]);
    init_k<<<(BB * K2H + 255) / 256, 256>>>((const float*)d_in[1]);
    mega<<<NBLK, NTHR>>>(p);
}

// round 6
// speedup vs baseline: 1.3646x; 1.3646x over previous
#include <cuda_runtime.h>
#include <math.h>
#include <stdint.h>

#define BB 256
#define HH 512
#define H4 2048
#define LEN 48
#define LOOKN 10
#define K2H 1024
#define STARTI 48
#define LABW 58
#define NBLK 256
#define NTHR 128

// ---- scratch layout (floats; tf32 u32 data stored in float slots) ----
constexpr size_t O_WISEQ = 0;
constexpr size_t O_MID2  = O_WISEQ + (size_t)BB*LEN*HH;
constexpr size_t O_Y     = O_MID2  + (size_t)BB*LEN*HH;
constexpr size_t O_HT0   = O_Y     + (size_t)BB*LEN*HH;
constexpr size_t O_HT1   = O_HT0   + (size_t)BB*K2H;
constexpr size_t O_HE0   = O_HT1   + (size_t)BB*K2H;
constexpr size_t O_HE1   = O_HE0   + (size_t)BB*K2H;
constexpr size_t O_HM0   = O_HE1   + (size_t)BB*K2H;
constexpr size_t O_HM1   = O_HM0   + (size_t)BB*K2H;
constexpr size_t O_DECIN = O_HM1   + (size_t)BB*K2H;
constexpr size_t O_WTWHO = O_DECIN + (size_t)BB*HH;
constexpr size_t O_TU    = O_WTWHO + (size_t)BB*K2H;
constexpr size_t O_SC    = O_TU    + (size_t)BB*HH;
constexpr size_t O_XM    = O_SC    + (size_t)BB*HH;
constexpr size_t O_LAB   = O_XM    + (size_t)BB*HH;
constexpr size_t O_BSPI  = O_LAB   + 1024;
constexpr size_t O_BTGI  = O_BSPI  + H4;
constexpr size_t O_BMDI  = O_BTGI  + H4;
constexpr size_t O_WTGCI = O_BMDI  + H4;
constexpr size_t O_WI32  = O_WTGCI + H4;
constexpr size_t O_WE32  = O_WI32  + (size_t)512*512;
constexpr size_t O_VD32  = O_WE32  + (size_t)512*1024;
constexpr size_t O_WX32  = O_VD32  + (size_t)512*512;
constexpr size_t O_WTWH32= O_WX32  + (size_t)512*512;
constexpr size_t O_SPIH  = O_WTWH32+ (size_t)1024*1024;
constexpr size_t O_SPHH  = O_SPIH  + (size_t)H4*512;
constexpr size_t O_TGX   = O_SPHH  + (size_t)H4*512;
constexpr size_t O_TGHH  = O_TGX   + (size_t)H4*512;
constexpr size_t O_MDIH  = O_TGHH  + (size_t)H4*512;
constexpr size_t O_MDHH  = O_MDIH  + (size_t)H4*512;
constexpr size_t G_TOTAL = O_MDHH  + (size_t)H4*512;

__device__ float g_buf[G_TOTAL];
__device__ unsigned g_arrive;
__device__ unsigned g_release;

__device__ __forceinline__ void gsync(unsigned ph)
{
    __syncthreads();
    if (threadIdx.x == 0) {
        __threadfence();
        unsigned arrived = atomicAdd(&g_arrive, 1u) + 1u;
        if (arrived == (unsigned)NBLK * ph) {
            atomicExch(&g_release, ph);
        } else {
            while (*(volatile unsigned*)&g_release < ph) { __nanosleep(64); }
        }
        __threadfence();
    }
    __syncthreads();
}

__device__ __forceinline__ uint32_t f2tf32(float x)
{
    uint32_t u;
    asm("cvt.rna.tf32.f32 %0, %1;" : "=r"(u) : "f"(x));
    return u;
}

__device__ __forceinline__ void mma_tf32(float* d,
    uint32_t a0, uint32_t a1, uint32_t a2, uint32_t a3,
    uint32_t b0, uint32_t b1)
{
    asm volatile(
        "mma.sync.aligned.m16n8k8.row.col.f32.tf32.tf32.f32 "
        "{%0,%1,%2,%3},{%4,%5,%6,%7},{%8,%9},{%0,%1,%2,%3};"
        : "+f"(d[0]), "+f"(d[1]), "+f"(d[2]), "+f"(d[3])
        : "r"(a0), "r"(a1), "r"(a2), "r"(a3), "r"(b0), "r"(b1));
}

struct Params {
    const float *inp;
    const float *Wi_b, *Vd_b, *Wx_b, *V_w, *V_b, *reg_w, *reg_b;
    float* out;
    float* gb;
};

// ---- tf32 tensor-core GEMM, block tile 32x64, warp grid 2x2 (warp tile 16x32) ----
// C = act( A1@W1^T + A2@W2^T + bias + add1 + add2 + r1u[m]*r1v[n] )
// mode 0 = store, 1 = tanh+store, 2 = fused LSTM (interleaved gates h*4+g):
//   reads old c from cin, writes h/c into outp (stride 1024), optional hout.
__device__ void gemm_mma(
    const float* __restrict__ A1, int lda1, const uint32_t* __restrict__ W1, int K1,
    const float* __restrict__ A2, int lda2, const uint32_t* __restrict__ W2, int K2,
    const float* __restrict__ bias,
    const float* __restrict__ add1, int ld1,
    const float* __restrict__ add2, int ld2,
    const float* __restrict__ r1u, const float* __restrict__ r1v,
    const float* __restrict__ cin,
    float* __restrict__ outp, int M, int N, int mode,
    float* __restrict__ hout, int hstride,
    uint32_t (*sA)[20], uint32_t (*sW)[20],
    int vbid, int vgrid)
{
    const int tid = threadIdx.x;
    const int wid = tid >> 5, lane = tid & 31;
    const int g = lane >> 2, tg = lane & 3;
    const int wm = (wid >> 1) << 4, wn = (wid & 1) << 5;
    const int am = tid >> 2, aq = (tid & 3) << 2;
    const int ws = tid >> 1, wq = (tid & 1) << 3;
    const int nct = N >> 6;
    const int ntiles = (M >> 5) * nct;

    for (int t = vbid; t < ntiles; t += vgrid) {
        const int m0 = (t / nct) << 5, n0 = (t % nct) << 6;
        float acc[4][4];
#pragma unroll
        for (int j = 0; j < 4; j++)
#pragma unroll
            for (int i = 0; i < 4; i++) acc[j][i] = 0.f;

        for (int seg = 0; seg < 2; ++seg) {
            const float* A = seg ? A2 : A1;
            if (!A) continue;
            const uint32_t* W = seg ? W2 : W1;
            const int lda = seg ? lda2 : lda1;
            const int K   = seg ? K2   : K1;

            float4 pa  = *(const float4*)(A + (size_t)(m0 + am) * lda + aq);
            uint4  pw0 = *(const uint4*)(W + (size_t)(n0 + ws) * K + wq);
            uint4  pw1 = *(const uint4*)(W + (size_t)(n0 + ws) * K + wq + 4);

            for (int k0 = 0; k0 < K; k0 += 16) {
                __syncthreads();
                sA[am][aq+0] = f2tf32(pa.x);
                sA[am][aq+1] = f2tf32(pa.y);
                sA[am][aq+2] = f2tf32(pa.z);
                sA[am][aq+3] = f2tf32(pa.w);
                *(uint4*)&sW[ws][wq]   = pw0;
                *(uint4*)&sW[ws][wq+4] = pw1;
                __syncthreads();
                const int kn = k0 + 16;
                if (kn < K) {
                    pa  = *(const float4*)(A + (size_t)(m0 + am) * lda + kn + aq);
                    pw0 = *(const uint4*)(W + (size_t)(n0 + ws) * K + kn + wq);
                    pw1 = *(const uint4*)(W + (size_t)(n0 + ws) * K + kn + wq + 4);
                }
                const uint32_t a0 = sA[wm+g][tg],    a1 = sA[wm+g+8][tg];
                const uint32_t a2 = sA[wm+g][tg+4],  a3 = sA[wm+g+8][tg+4];
                const uint32_t a4 = sA[wm+g][8+tg],  a5 = sA[wm+g+8][8+tg];
                const uint32_t a6 = sA[wm+g][12+tg], a7 = sA[wm+g+8][12+tg];
#pragma unroll
                for (int j = 0; j < 4; ++j) {
                    const int nr = wn + 8*j + g;
                    mma_tf32(acc[j], a0, a1, a2, a3, sW[nr][tg],   sW[nr][tg+4]);
                    mma_tf32(acc[j], a4, a5, a6, a7, sW[nr][8+tg], sW[nr][12+tg]);
                }
            }
        }

        const int mA = m0 + wm + g, mB = mA + 8;
        if (mode < 2) {
#pragma unroll
            for (int j = 0; j < 4; ++j) {
                const int nc0 = n0 + wn + 8*j + 2*tg, nc1 = nc0 + 1;
                float v00 = acc[j][0], v01 = acc[j][1];
                float v10 = acc[j][2], v11 = acc[j][3];
                if (bias) { v00 += bias[nc0]; v01 += bias[nc1];
                            v10 += bias[nc0]; v11 += bias[nc1]; }
                if (add1) { v00 += add1[(size_t)mA*ld1+nc0]; v01 += add1[(size_t)mA*ld1+nc1];
                            v10 += add1[(size_t)mB*ld1+nc0]; v11 += add1[(size_t)mB*ld1+nc1]; }
                if (add2) { v00 += add2[(size_t)mA*ld2+nc0]; v01 += add2[(size_t)mA*ld2+nc1];
                            v10 += add2[(size_t)mB*ld2+nc0]; v11 += add2[(size_t)mB*ld2+nc1]; }
                if (mode == 1) {
                    v00 = tanhf(v00); v01 = tanhf(v01);
                    v10 = tanhf(v10); v11 = tanhf(v11);
                }
                outp[(size_t)mA*N + nc0] = v00; outp[(size_t)mA*N + nc1] = v01;
                outp[(size_t)mB*N + nc0] = v10; outp[(size_t)mB*N + nc1] = v11;
            }
        } else {
#pragma unroll
            for (int j = 0; j < 4; ++j) {
                const int nb = n0 + wn + 8*j;
                const int nc0 = nb + 2*tg, nc1 = nc0 + 1;
                float v00 = acc[j][0] + bias[nc0], v01 = acc[j][1] + bias[nc1];
                float v10 = acc[j][2] + bias[nc0], v11 = acc[j][3] + bias[nc1];
                if (r1u) {
                    const float ra = r1u[mA], rb = r1u[mB];
                    v00 += ra * r1v[nc0]; v01 += ra * r1v[nc1];
                    v10 += rb * r1v[nc0]; v11 += rb * r1v[nc1];
                }
                const float t00 = __shfl_xor_sync(0xffffffffu, v00, 1);
                const float t01 = __shfl_xor_sync(0xffffffffu, v01, 1);
                const float t10 = __shfl_xor_sync(0xffffffffu, v10, 1);
                const float t11 = __shfl_xor_sync(0xffffffffu, v11, 1);
                int m; float fi, ff, fg, fo;
                if ((tg & 1) == 0) { m = mA; fi = v00; ff = v01; fg = t00; fo = t01; }
                else               { m = mB; fi = t10; ff = t11; fg = v10; fo = v11; }
                const int h = (nb >> 2) + (tg >> 1);
                const float cold = cin[(size_t)m*1024 + 512 + h];
                const float si = 1.f / (1.f + expf(-fi));
                const float sf = 1.f / (1.f + expf(-ff));
                const float so = 1.f / (1.f + expf(-fo));
                const float c2 = sf * cold + si * tanhf(fg);
                const float hn = so * tanhf(c2);
                outp[(size_t)m*1024 + h]       = hn;
                outp[(size_t)m*1024 + 512 + h] = c2;
                if (hout) hout[(size_t)m*hstride + h] = hn;
            }
        }
        __syncthreads();
    }
}

__device__ void softmax_dev(const float* __restrict__ sc, const float* __restrict__ x,
                            int t, float* __restrict__ xm, float* red)
{
    const int b = blockIdx.x, tid = threadIdx.x;
    const int lane = tid & 31, wid = tid >> 5;
    const float* sr = sc + (size_t)b * 512;
    float v0 = sr[tid], v1 = sr[tid+128], v2 = sr[tid+256], v3 = sr[tid+384];
    float m = fmaxf(fmaxf(v0, v1), fmaxf(v2, v3));
#pragma unroll
    for (int o = 16; o; o >>= 1) m = fmaxf(m, __shfl_xor_sync(0xffffffffu, m, o));
    if (lane == 0) red[wid] = m;
    __syncthreads();
    const float bm = fmaxf(fmaxf(red[0], red[1]), fmaxf(red[2], red[3]));
    __syncthreads();
    const float e0 = expf(v0-bm), e1 = expf(v1-bm), e2 = expf(v2-bm), e3 = expf(v3-bm);
    float s = e0 + e1 + e2 + e3;
#pragma unroll
    for (int o = 16; o; o >>= 1) s += __shfl_xor_sync(0xffffffffu, s, o);
    if (lane == 0) red[wid] = s;
    __syncthreads();
    const float inv = 1.f / (red[0] + red[1] + red[2] + red[3]);
    const float* xr = x + ((size_t)b * LEN + t) * 512;
    xm[(size_t)b*512 + tid]     = xr[tid]     * e0 * inv;
    xm[(size_t)b*512 + tid+128] = xr[tid+128] * e1 * inv;
    xm[(size_t)b*512 + tid+256] = xr[tid+256] * e2 * inv;
    xm[(size_t)b*512 + tid+384] = xr[tid+384] * e3 * inv;
    __syncthreads();
}

__device__ void dec_dev(const float* __restrict__ y, const float* __restrict__ wh,
                        const float* __restrict__ Vw, const float* __restrict__ Vb,
                        const float* __restrict__ mid2, float* __restrict__ decin,
                        float* ssc)
{
    const int b = blockIdx.x, tid = threadIdx.x;
    const int lane = tid & 31, wid = tid >> 5;
    for (int l = wid; l < LEN; l += 4) {
        const float* yr = y + ((size_t)b * LEN + l) * HH;
        float pv = 0.f;
        for (int h = lane; h < HH; h += 32)
            pv += tanhf(wh[(size_t)b * K2H + h] + yr[h]) * Vw[h];
#pragma unroll
        for (int o = 16; o; o >>= 1) pv += __shfl_xor_sync(0xffffffffu, pv, o);
        if (lane == 0) ssc[l] = pv + Vb[0];
    }
    __syncthreads();
    float a0 = 0.f, a1 = 0.f, a2 = 0.f, a3 = 0.f;
    for (int l = 0; l < LEN; l++) {
        const float s = ssc[l];
        const float* mr = mid2 + ((size_t)b * LEN + l) * HH;
        a0 += s * mr[tid];     a1 += s * mr[tid+128];
        a2 += s * mr[tid+256]; a3 += s * mr[tid+384];
    }
    decin[(size_t)b*HH + tid]     = a0;
    decin[(size_t)b*HH + tid+128] = a1;
    decin[(size_t)b*HH + tid+256] = a2;
    decin[(size_t)b*HH + tid+384] = a3;
    __syncthreads();
}

// ---- persistent mega kernel ----
__global__ __launch_bounds__(NTHR) void mega(Params p)
{
    __shared__ uint32_t sA[32][20];
    __shared__ uint32_t sW[64][20];
    __shared__ float red[4];
    __shared__ float ssc[LEN];

    float* gb    = p.gb;
    float* wiseq = gb + O_WISEQ;  float* mid2  = gb + O_MID2;
    float* ybuf  = gb + O_Y;
    float* ht0   = gb + O_HT0;    float* ht1   = gb + O_HT1;
    float* he0   = gb + O_HE0;    float* he1   = gb + O_HE1;
    float* hm0   = gb + O_HM0;    float* hm1   = gb + O_HM1;
    float* decin = gb + O_DECIN;  float* wtwho = gb + O_WTWHO;
    float* tu    = gb + O_TU;     float* sc    = gb + O_SC;
    float* xm    = gb + O_XM;     float* lab   = gb + O_LAB;
    float* bspi  = gb + O_BSPI;   float* btgi  = gb + O_BTGI;
    float* bmdi  = gb + O_BMDI;   float* wtgci = gb + O_WTGCI;
    const uint32_t* WI32   = (const uint32_t*)(gb + O_WI32);
    const uint32_t* WE32   = (const uint32_t*)(gb + O_WE32);
    const uint32_t* VD32   = (const uint32_t*)(gb + O_VD32);
    const uint32_t* WX32   = (const uint32_t*)(gb + O_WX32);
    const uint32_t* WTWH32 = (const uint32_t*)(gb + O_WTWH32);
    const uint32_t* SPIH   = (const uint32_t*)(gb + O_SPIH);
    const uint32_t* SPHH   = (const uint32_t*)(gb + O_SPHH);
    const uint32_t* TGX    = (const uint32_t*)(gb + O_TGX);
    const uint32_t* TGHH   = (const uint32_t*)(gb + O_TGHH);
    const uint32_t* MDIH   = (const uint32_t*)(gb + O_MDIH);
    const uint32_t* MDHH   = (const uint32_t*)(gb + O_MDHH);

    unsigned ph = 0;

    // wiseq = input @ Wi^T + Wi_b
    gemm_mma(p.inp, 512, WI32, 512, nullptr, 0, nullptr, 0,
             p.Wi_b, nullptr, 0, nullptr, 0, nullptr, nullptr, nullptr,
             wiseq, BB*LEN, HH, 0, nullptr, 0, sA, sW, blockIdx.x, NBLK);
    gsync(++ph);

    for (int k = 0; k < LOOKN; k++) {
        float* htin  = (k & 1) ? ht1 : ht0;
        float* htout = (k & 1) ? ht0 : ht1;

        // tg gates (fused LSTM): decin@TGX^T + htin@TGHH^T + b + lab*wtgc
        gemm_mma(decin, 512, TGX, 512, htin, K2H, TGHH, 512,
                 btgi, nullptr, 0, nullptr, 0, lab, wtgci, htin,
                 htout, BB, H4, 2, nullptr, 0, sA, sW, blockIdx.x, NBLK);
        gsync(++ph);

        // packed: wtwh gemm (blocks 0-127) | target (128) | zero states (129-255)
        if (blockIdx.x < 128) {
            gemm_mma(htout, K2H, WTWH32, K2H, nullptr, 0, nullptr, 0,
                     nullptr, nullptr, 0, nullptr, 0, nullptr, nullptr, nullptr,
                     wtwho, BB, K2H, 0, nullptr, 0, sA, sW, blockIdx.x, 128);
        } else if (blockIdx.x == 128) {
            const int lane = threadIdx.x & 31, wid = threadIdx.x >> 5;
            for (int r = wid; r < BB; r += 4) {
                float s = 0.f;
                for (int h = lane; h < HH; h += 32)
                    s += htout[(size_t)r * K2H + h] * p.reg_w[h];
#pragma unroll
                for (int o = 16; o; o >>= 1) s += __shfl_xor_sync(0xffffffffu, s, o);
                if (lane == 0) {
                    const float tv = s + p.reg_b[0];
                    p.out[r * LOOKN + k] = tv;
                    lab[r] = tv;
                }
            }
        } else {
            const int base = (blockIdx.x - 129) * NTHR + threadIdx.x;
            for (int i = base; i < BB * K2H; i += 127 * NTHR) {
                he0[i] = 0.f;
                hm0[i] = 0.f;
            }
        }
        gsync(++ph);

        for (int l = 0; l < LEN; l++) {
            float* hein  = (l & 1) ? he1 : he0;
            float* heout = (l & 1) ? he0 : he1;
            float* hmin  = (l & 1) ? hm1 : hm0;
            float* hmout = (l & 1) ? hm0 : hm1;

            // tu = tanh(hein@We^T + wi_x[l] + wt)
            gemm_mma(hein, K2H, WE32, K2H, nullptr, 0, nullptr, 0,
                     nullptr, wiseq + (size_t)l * HH, LEN*HH, wtwho, K2H,
                     nullptr, nullptr, nullptr,
                     tu, BB, HH, 1, nullptr, 0, sA, sW, blockIdx.x, NBLK);
            gsync(++ph);
            // sc = tu @ Vd^T + Vd_b
            gemm_mma(tu, 512, VD32, 512, nullptr, 0, nullptr, 0,
                     p.Vd_b, nullptr, 0, nullptr, 0, nullptr, nullptr, nullptr,
                     sc, BB, HH, 0, nullptr, 0, sA, sW, blockIdx.x, NBLK);
            gsync(++ph);
            softmax_dev(sc, p.inp, l, xm, red);
            gsync(++ph);
            // sp gates (fused LSTM)
            gemm_mma(xm, 512, SPIH, 512, hein, K2H, SPHH, 512,
                     bspi, nullptr, 0, nullptr, 0, nullptr, nullptr, hein,
                     heout, BB, H4, 2, nullptr, 0, sA, sW, blockIdx.x, NBLK);
            gsync(++ph);
            // mid gates (fused LSTM) + mid2 output
            gemm_mma(heout, K2H, MDIH, 512, hmin, K2H, MDHH, 512,
                     bmdi, nullptr, 0, nullptr, 0, nullptr, nullptr, hmin,
                     hmout, BB, H4, 2, mid2 + (size_t)l * HH, LEN*HH,
                     sA, sW, blockIdx.x, NBLK);
            gsync(++ph);
        }
        // y = mid2 @ Wx^T + Wx_b
        gemm_mma(mid2, 512, WX32, 512, nullptr, 0, nullptr, 0,
                 p.Wx_b, nullptr, 0, nullptr, 0, nullptr, nullptr, nullptr,
                 ybuf, BB*LEN, HH, 0, nullptr, 0, sA, sW, blockIdx.x, NBLK);
        gsync(++ph);
        dec_dev(ybuf, wtwho + 512, p.V_w, p.V_b, mid2, decin, ssc);
        gsync(++ph);
    }
}

// ---- prep: tf32 conversions, gate interleaving, bias combines ----
__global__ __launch_bounds__(256) void prep_k(
    const float* bihsp, const float* bhhsp, const float* bihtg, const float* bhhtg,
    const float* bihmid, const float* bhhmid, const float* wihtg,
    const float* wtw, const float* whw,
    const float* wisp, const float* whsp, const float* whtg,
    const float* wimd, const float* whmd,
    const float* wiw, const float* wew, const float* vdw, const float* wxw)
{
    const int nt = gridDim.x * 256;
    const int gid = blockIdx.x * 256 + threadIdx.x;
    uint32_t* WI32   = (uint32_t*)(g_buf + O_WI32);
    uint32_t* WE32   = (uint32_t*)(g_buf + O_WE32);
    uint32_t* VD32   = (uint32_t*)(g_buf + O_VD32);
    uint32_t* WX32   = (uint32_t*)(g_buf + O_WX32);
    uint32_t* WTWH32 = (uint32_t*)(g_buf + O_WTWH32);
    uint32_t* SPIH   = (uint32_t*)(g_buf + O_SPIH);
    uint32_t* SPHH   = (uint32_t*)(g_buf + O_SPHH);
    uint32_t* TGX    = (uint32_t*)(g_buf + O_TGX);
    uint32_t* TGHH   = (uint32_t*)(g_buf + O_TGHH);
    uint32_t* MDIH   = (uint32_t*)(g_buf + O_MDIH);
    uint32_t* MDHH   = (uint32_t*)(g_buf + O_MDHH);

    for (int i = gid; i < 512*512; i += nt) {
        WI32[i] = f2tf32(wiw[i]);
        VD32[i] = f2tf32(vdw[i]);
        WX32[i] = f2tf32(wxw[i]);
    }
    for (int i = gid; i < 512*1024; i += nt) WE32[i] = f2tf32(wew[i]);
    for (int i = gid; i < 1024*1024; i += nt) {
        const int r = i >> 10, c = i & 1023;
        WTWH32[i] = f2tf32(r < 512 ? wtw[(size_t)r*1024 + c]
                                   : whw[(size_t)(r-512)*1024 + c]);
    }
    for (int i = gid; i < H4*512; i += nt) {
        const int rp = i >> 9, kk = i & 511;
        const int h = rp >> 2, gg = rp & 3;
        const size_t src = (size_t)(gg * 512 + h);
        SPIH[i] = f2tf32(wisp[src*512 + kk]);
        SPHH[i] = f2tf32(whsp[src*512 + kk]);
        TGHH[i] = f2tf32(whtg[src*512 + kk]);
        MDIH[i] = f2tf32(wimd[src*512 + kk]);
        MDHH[i] = f2tf32(whmd[src*512 + kk]);
        TGX[i]  = f2tf32(wihtg[src*513 + 1 + kk]);
    }
    for (int i = gid; i < H4; i += nt) {
        const int h = i >> 2, gg = i & 3;
        const int s = gg * 512 + h;
        g_buf[O_BSPI + i]  = bihsp[s] + bhhsp[s];
        g_buf[O_BTGI + i]  = bihtg[s] + bhhtg[s];
        g_buf[O_BMDI + i]  = bihmid[s] + bhhmid[s];
        g_buf[O_WTGCI + i] = wihtg[(size_t)s * 513];
    }
}

__global__ __launch_bounds__(256) void init_k(const float* __restrict__ labp)
{
    const int i = blockIdx.x * 256 + threadIdx.x;
    if (i == 0) { g_arrive = 0u; g_release = 0u; }
    if (i < BB * K2H) g_buf[O_HT0 + i] = 0.f;
    if (i < BB * HH)  g_buf[O_DECIN + i] = 0.f;
    if (i < BB)       g_buf[O_LAB + i] = labp[(size_t)i * LABW + STARTI];
}

extern "C" void kernel_launch(void* const* d_in, const int* in_sizes, int n_in,
                              void* d_out, int out_size)
{
    Params p;
    p.inp   = (const float*)d_in[0];
    p.Wi_b  = (const float*)d_in[15];
    p.Vd_b  = (const float*)d_in[19];
    p.Wx_b  = (const float*)d_in[21];
    p.V_w   = (const float*)d_in[23];
    p.V_b   = (const float*)d_in[24];
    p.reg_w = (const float*)d_in[25];
    p.reg_b = (const float*)d_in[26];
    p.out   = (float*)d_out;

    float* gb = nullptr;
    cudaGetSymbolAddress((void**)&gb, g_buf);
    p.gb = gb;

    prep_k<<<2048, 256>>>(
        (const float*)d_in[4], (const float*)d_in[5], (const float*)d_in[8],
        (const float*)d_in[9], (const float*)d_in[12], (const float*)d_in[13],
        (const float*)d_in[6], (const float*)d_in[17], (const float*)d_in[22],
        (const float*)d_in[2], (const float*)d_in[3], (const float*)d_in[7],
        (const float*)d_in[10], (const float*)d_in[11],
        (const float*)d_in[14], (const float*)d_in[16],
        (const float*)d_in[18], (const float*)d_in[20]);
    init_k<<<(BB * K2H + 255) / 256, 256>>>((const float*)d_in[1]);
    mega<<<NBLK, NTHR>>>(p);
}

// round 7
// speedup vs baseline: 1.4013x; 1.0269x over previous
#include <cuda_runtime.h>
#include <math.h>
#include <stdint.h>

#define BB 256
#define HH 512
#define H4 2048
#define LEN 48
#define LOOKN 10
#define K2H 1024
#define STARTI 48
#define LABW 58
#define NBLK 296
#define NTHR 128
#define NSUB 8
#define SUBCNT (NBLK / NSUB)

// ---- scratch layout (floats; tf32 u32 data stored in float slots) ----
constexpr size_t O_WISEQ = 0;
constexpr size_t O_MID2  = O_WISEQ + (size_t)BB*LEN*HH;
constexpr size_t O_Y     = O_MID2  + (size_t)BB*LEN*HH;
constexpr size_t O_HT0   = O_Y     + (size_t)BB*LEN*HH;
constexpr size_t O_HT1   = O_HT0   + (size_t)BB*K2H;
constexpr size_t O_HE0   = O_HT1   + (size_t)BB*K2H;
constexpr size_t O_HE1   = O_HE0   + (size_t)BB*K2H;
constexpr size_t O_HM0   = O_HE1   + (size_t)BB*K2H;
constexpr size_t O_HM1   = O_HM0   + (size_t)BB*K2H;
constexpr size_t O_DECIN = O_HM1   + (size_t)BB*K2H;
constexpr size_t O_WTWHO = O_DECIN + (size_t)BB*HH;
constexpr size_t O_TU    = O_WTWHO + (size_t)BB*K2H;
constexpr size_t O_SC    = O_TU    + (size_t)BB*HH;
constexpr size_t O_XM    = O_SC    + (size_t)BB*HH;
constexpr size_t O_LAB   = O_XM    + (size_t)BB*HH;
constexpr size_t O_BSPI  = O_LAB   + 1024;
constexpr size_t O_BTGI  = O_BSPI  + H4;
constexpr size_t O_BMDI  = O_BTGI  + H4;
constexpr size_t O_WTGCI = O_BMDI  + H4;
constexpr size_t O_WI32  = O_WTGCI + H4;
constexpr size_t O_WE32  = O_WI32  + (size_t)512*512;
constexpr size_t O_VD32  = O_WE32  + (size_t)512*1024;
constexpr size_t O_WX32  = O_VD32  + (size_t)512*512;
constexpr size_t O_WTWH32= O_WX32  + (size_t)512*512;
constexpr size_t O_SPIH  = O_WTWH32+ (size_t)1024*1024;
constexpr size_t O_SPHH  = O_SPIH  + (size_t)H4*512;
constexpr size_t O_TGX   = O_SPHH  + (size_t)H4*512;
constexpr size_t O_TGHH  = O_TGX   + (size_t)H4*512;
constexpr size_t O_MDIH  = O_TGHH  + (size_t)H4*512;
constexpr size_t O_MDHH  = O_MDIH  + (size_t)H4*512;
constexpr size_t G_TOTAL = O_MDHH  + (size_t)H4*512;

__device__ float g_buf[G_TOTAL];

// hierarchical barrier state: 8 sub-counters padded to separate 128B lines
__device__ __align__(128) unsigned g_arr[NSUB * 32];
__device__ unsigned g_master;
__device__ unsigned g_rel;

__device__ __forceinline__ void gsync(unsigned ph)
{
    __syncthreads();
    if (threadIdx.x == 0) {
        __threadfence();
        const unsigned sub = blockIdx.x & (NSUB - 1);
        const unsigned v = atomicAdd(&g_arr[sub * 32], 1u) + 1u;
        if (v == ph * (unsigned)SUBCNT) {
            const unsigned m = atomicAdd(&g_master, 1u) + 1u;
            if (m == ph * (unsigned)NSUB) {
                atomicExch(&g_rel, ph);
            }
        }
        while (*(volatile unsigned*)&g_rel < ph) { __nanosleep(64); }
        __threadfence();
    }
    __syncthreads();
}

__device__ __forceinline__ uint32_t f2tf32(float x)
{
    uint32_t u;
    asm("cvt.rna.tf32.f32 %0, %1;" : "=r"(u) : "f"(x));
    return u;
}

__device__ __forceinline__ void mma_tf32(float* d,
    uint32_t a0, uint32_t a1, uint32_t a2, uint32_t a3,
    uint32_t b0, uint32_t b1)
{
    asm volatile(
        "mma.sync.aligned.m16n8k8.row.col.f32.tf32.tf32.f32 "
        "{%0,%1,%2,%3},{%4,%5,%6,%7},{%8,%9},{%0,%1,%2,%3};"
        : "+f"(d[0]), "+f"(d[1]), "+f"(d[2]), "+f"(d[3])
        : "r"(a0), "r"(a1), "r"(a2), "r"(a3), "r"(b0), "r"(b1));
}

struct Params {
    const float *inp;
    const float *Wi_b, *Vd_b, *Wx_b, *V_w, *V_b, *reg_w, *reg_b;
    float* out;
    float* gb;
};

// ---- tf32 tensor-core GEMM, block tile 32x64, warp grid 2x2 (warp tile 16x32) ----
// C = act( A1@W1^T + A2@W2^T + bias + add1 + add2 + r1u[m]*r1v[n] )
// mode 0 = store, 1 = tanh+store, 2 = fused LSTM (interleaved gates h*4+g):
//   reads old c from cin, writes h/c into outp (stride 1024), optional hout.
__device__ void gemm_mma(
    const float* __restrict__ A1, int lda1, const uint32_t* __restrict__ W1, int K1,
    const float* __restrict__ A2, int lda2, const uint32_t* __restrict__ W2, int K2,
    const float* __restrict__ bias,
    const float* __restrict__ add1, int ld1,
    const float* __restrict__ add2, int ld2,
    const float* __restrict__ r1u, const float* __restrict__ r1v,
    const float* __restrict__ cin,
    float* __restrict__ outp, int M, int N, int mode,
    float* __restrict__ hout, int hstride,
    uint32_t (*sA)[20], uint32_t (*sW)[20],
    int vbid, int vgrid)
{
    const int tid = threadIdx.x;
    const int wid = tid >> 5, lane = tid & 31;
    const int g = lane >> 2, tg = lane & 3;
    const int wm = (wid >> 1) << 4, wn = (wid & 1) << 5;
    const int am = tid >> 2, aq = (tid & 3) << 2;
    const int ws = tid >> 1, wq = (tid & 1) << 3;
    const int nct = N >> 6;
    const int ntiles = (M >> 5) * nct;

    for (int t = vbid; t < ntiles; t += vgrid) {
        const int m0 = (t / nct) << 5, n0 = (t % nct) << 6;
        float acc[4][4];
#pragma unroll
        for (int j = 0; j < 4; j++)
#pragma unroll
            for (int i = 0; i < 4; i++) acc[j][i] = 0.f;

        for (int seg = 0; seg < 2; ++seg) {
            const float* A = seg ? A2 : A1;
            if (!A) continue;
            const uint32_t* W = seg ? W2 : W1;
            const int lda = seg ? lda2 : lda1;
            const int K   = seg ? K2   : K1;

            float4 pa  = *(const float4*)(A + (size_t)(m0 + am) * lda + aq);
            uint4  pw0 = *(const uint4*)(W + (size_t)(n0 + ws) * K + wq);
            uint4  pw1 = *(const uint4*)(W + (size_t)(n0 + ws) * K + wq + 4);

            for (int k0 = 0; k0 < K; k0 += 16) {
                __syncthreads();
                sA[am][aq+0] = f2tf32(pa.x);
                sA[am][aq+1] = f2tf32(pa.y);
                sA[am][aq+2] = f2tf32(pa.z);
                sA[am][aq+3] = f2tf32(pa.w);
                *(uint4*)&sW[ws][wq]   = pw0;
                *(uint4*)&sW[ws][wq+4] = pw1;
                __syncthreads();
                const int kn = k0 + 16;
                if (kn < K) {
                    pa  = *(const float4*)(A + (size_t)(m0 + am) * lda + kn + aq);
                    pw0 = *(const uint4*)(W + (size_t)(n0 + ws) * K + kn + wq);
                    pw1 = *(const uint4*)(W + (size_t)(n0 + ws) * K + kn + wq + 4);
                }
                const uint32_t a0 = sA[wm+g][tg],    a1 = sA[wm+g+8][tg];
                const uint32_t a2 = sA[wm+g][tg+4],  a3 = sA[wm+g+8][tg+4];
                const uint32_t a4 = sA[wm+g][8+tg],  a5 = sA[wm+g+8][8+tg];
                const uint32_t a6 = sA[wm+g][12+tg], a7 = sA[wm+g+8][12+tg];
#pragma unroll
                for (int j = 0; j < 4; ++j) {
                    const int nr = wn + 8*j + g;
                    mma_tf32(acc[j], a0, a1, a2, a3, sW[nr][tg],   sW[nr][tg+4]);
                    mma_tf32(acc[j], a4, a5, a6, a7, sW[nr][8+tg], sW[nr][12+tg]);
                }
            }
        }

        const int mA = m0 + wm + g, mB = mA + 8;
        if (mode < 2) {
#pragma unroll
            for (int j = 0; j < 4; ++j) {
                const int nc0 = n0 + wn + 8*j + 2*tg, nc1 = nc0 + 1;
                float v00 = acc[j][0], v01 = acc[j][1];
                float v10 = acc[j][2], v11 = acc[j][3];
                if (bias) { v00 += bias[nc0]; v01 += bias[nc1];
                            v10 += bias[nc0]; v11 += bias[nc1]; }
                if (add1) { v00 += add1[(size_t)mA*ld1+nc0]; v01 += add1[(size_t)mA*ld1+nc1];
                            v10 += add1[(size_t)mB*ld1+nc0]; v11 += add1[(size_t)mB*ld1+nc1]; }
                if (add2) { v00 += add2[(size_t)mA*ld2+nc0]; v01 += add2[(size_t)mA*ld2+nc1];
                            v10 += add2[(size_t)mB*ld2+nc0]; v11 += add2[(size_t)mB*ld2+nc1]; }
                if (mode == 1) {
                    v00 = tanhf(v00); v01 = tanhf(v01);
                    v10 = tanhf(v10); v11 = tanhf(v11);
                }
                outp[(size_t)mA*N + nc0] = v00; outp[(size_t)mA*N + nc1] = v01;
                outp[(size_t)mB*N + nc0] = v10; outp[(size_t)mB*N + nc1] = v11;
            }
        } else {
#pragma unroll
            for (int j = 0; j < 4; ++j) {
                const int nb = n0 + wn + 8*j;
                const int nc0 = nb + 2*tg, nc1 = nc0 + 1;
                float v00 = acc[j][0] + bias[nc0], v01 = acc[j][1] + bias[nc1];
                float v10 = acc[j][2] + bias[nc0], v11 = acc[j][3] + bias[nc1];
                if (r1u) {
                    const float ra = r1u[mA], rb = r1u[mB];
                    v00 += ra * r1v[nc0]; v01 += ra * r1v[nc1];
                    v10 += rb * r1v[nc0]; v11 += rb * r1v[nc1];
                }
                const float t00 = __shfl_xor_sync(0xffffffffu, v00, 1);
                const float t01 = __shfl_xor_sync(0xffffffffu, v01, 1);
                const float t10 = __shfl_xor_sync(0xffffffffu, v10, 1);
                const float t11 = __shfl_xor_sync(0xffffffffu, v11, 1);
                int m; float fi, ff, fg, fo;
                if ((tg & 1) == 0) { m = mA; fi = v00; ff = v01; fg = t00; fo = t01; }
                else               { m = mB; fi = t10; ff = t11; fg = v10; fo = v11; }
                const int h = (nb >> 2) + (tg >> 1);
                const float cold = cin[(size_t)m*1024 + 512 + h];
                const float si = 1.f / (1.f + expf(-fi));
                const float sf = 1.f / (1.f + expf(-ff));
                const float so = 1.f / (1.f + expf(-fo));
                const float c2 = sf * cold + si * tanhf(fg);
                const float hn = so * tanhf(c2);
                outp[(size_t)m*1024 + h]       = hn;
                outp[(size_t)m*1024 + 512 + h] = c2;
                if (hout) hout[(size_t)m*hstride + h] = hn;
            }
        }
        __syncthreads();
    }
}

__device__ void softmax_dev(const float* __restrict__ sc, const float* __restrict__ x,
                            int t, float* __restrict__ xm, float* red)
{
    const int b = blockIdx.x, tid = threadIdx.x;
    const int lane = tid & 31, wid = tid >> 5;
    const float* sr = sc + (size_t)b * 512;
    float v0 = sr[tid], v1 = sr[tid+128], v2 = sr[tid+256], v3 = sr[tid+384];
    float m = fmaxf(fmaxf(v0, v1), fmaxf(v2, v3));
#pragma unroll
    for (int o = 16; o; o >>= 1) m = fmaxf(m, __shfl_xor_sync(0xffffffffu, m, o));
    if (lane == 0) red[wid] = m;
    __syncthreads();
    const float bm = fmaxf(fmaxf(red[0], red[1]), fmaxf(red[2], red[3]));
    __syncthreads();
    const float e0 = expf(v0-bm), e1 = expf(v1-bm), e2 = expf(v2-bm), e3 = expf(v3-bm);
    float s = e0 + e1 + e2 + e3;
#pragma unroll
    for (int o = 16; o; o >>= 1) s += __shfl_xor_sync(0xffffffffu, s, o);
    if (lane == 0) red[wid] = s;
    __syncthreads();
    const float inv = 1.f / (red[0] + red[1] + red[2] + red[3]);
    const float* xr = x + ((size_t)b * LEN + t) * 512;
    xm[(size_t)b*512 + tid]     = xr[tid]     * e0 * inv;
    xm[(size_t)b*512 + tid+128] = xr[tid+128] * e1 * inv;
    xm[(size_t)b*512 + tid+256] = xr[tid+256] * e2 * inv;
    xm[(size_t)b*512 + tid+384] = xr[tid+384] * e3 * inv;
    __syncthreads();
}

__device__ void dec_dev(const float* __restrict__ y, const float* __restrict__ wh,
                        const float* __restrict__ Vw, const float* __restrict__ Vb,
                        const float* __restrict__ mid2, float* __restrict__ decin,
                        float* ssc)
{
    const int b = blockIdx.x, tid = threadIdx.x;
    const int lane = tid & 31, wid = tid >> 5;
    for (int l = wid; l < LEN; l += 4) {
        const float* yr = y + ((size_t)b * LEN + l) * HH;
        float pv = 0.f;
        for (int h = lane; h < HH; h += 32)
            pv += tanhf(wh[(size_t)b * K2H + h] + yr[h]) * Vw[h];
#pragma unroll
        for (int o = 16; o; o >>= 1) pv += __shfl_xor_sync(0xffffffffu, pv, o);
        if (lane == 0) ssc[l] = pv + Vb[0];
    }
    __syncthreads();
    float a0 = 0.f, a1 = 0.f, a2 = 0.f, a3 = 0.f;
    for (int l = 0; l < LEN; l++) {
        const float s = ssc[l];
        const float* mr = mid2 + ((size_t)b * LEN + l) * HH;
        a0 += s * mr[tid];     a1 += s * mr[tid+128];
        a2 += s * mr[tid+256]; a3 += s * mr[tid+384];
    }
    decin[(size_t)b*HH + tid]     = a0;
    decin[(size_t)b*HH + tid+128] = a1;
    decin[(size_t)b*HH + tid+256] = a2;
    decin[(size_t)b*HH + tid+384] = a3;
    __syncthreads();
}

// ---- persistent mega kernel ----
__global__ __launch_bounds__(NTHR) void mega(Params p)
{
    __shared__ uint32_t sA[32][20];
    __shared__ uint32_t sW[64][20];
    __shared__ float red[4];
    __shared__ float ssc[LEN];

    float* gb    = p.gb;
    float* wiseq = gb + O_WISEQ;  float* mid2  = gb + O_MID2;
    float* ybuf  = gb + O_Y;
    float* ht0   = gb + O_HT0;    float* ht1   = gb + O_HT1;
    float* he0   = gb + O_HE0;    float* he1   = gb + O_HE1;
    float* hm0   = gb + O_HM0;    float* hm1   = gb + O_HM1;
    float* decin = gb + O_DECIN;  float* wtwho = gb + O_WTWHO;
    float* tu    = gb + O_TU;     float* sc    = gb + O_SC;
    float* xm    = gb + O_XM;     float* lab   = gb + O_LAB;
    float* bspi  = gb + O_BSPI;   float* btgi  = gb + O_BTGI;
    float* bmdi  = gb + O_BMDI;   float* wtgci = gb + O_WTGCI;
    const uint32_t* WI32   = (const uint32_t*)(gb + O_WI32);
    const uint32_t* WE32   = (const uint32_t*)(gb + O_WE32);
    const uint32_t* VD32   = (const uint32_t*)(gb + O_VD32);
    const uint32_t* WX32   = (const uint32_t*)(gb + O_WX32);
    const uint32_t* WTWH32 = (const uint32_t*)(gb + O_WTWH32);
    const uint32_t* SPIH   = (const uint32_t*)(gb + O_SPIH);
    const uint32_t* SPHH   = (const uint32_t*)(gb + O_SPHH);
    const uint32_t* TGX    = (const uint32_t*)(gb + O_TGX);
    const uint32_t* TGHH   = (const uint32_t*)(gb + O_TGHH);
    const uint32_t* MDIH   = (const uint32_t*)(gb + O_MDIH);
    const uint32_t* MDHH   = (const uint32_t*)(gb + O_MDHH);

    unsigned ph = 0;

    // wiseq = input @ Wi^T + Wi_b
    gemm_mma(p.inp, 512, WI32, 512, nullptr, 0, nullptr, 0,
             p.Wi_b, nullptr, 0, nullptr, 0, nullptr, nullptr, nullptr,
             wiseq, BB*LEN, HH, 0, nullptr, 0, sA, sW, blockIdx.x, NBLK);
    gsync(++ph);

    for (int k = 0; k < LOOKN; k++) {
        float* htin  = (k & 1) ? ht1 : ht0;
        float* htout = (k & 1) ? ht0 : ht1;

        // tg gates (fused LSTM): decin@TGX^T + htin@TGHH^T + b + lab*wtgc
        gemm_mma(decin, 512, TGX, 512, htin, K2H, TGHH, 512,
                 btgi, nullptr, 0, nullptr, 0, lab, wtgci, htin,
                 htout, BB, H4, 2, nullptr, 0, sA, sW, blockIdx.x, NBLK);
        gsync(++ph);

        // packed: wtwh gemm (blocks 0-127) | target (128) | zero states (129-295)
        if (blockIdx.x < 128) {
            gemm_mma(htout, K2H, WTWH32, K2H, nullptr, 0, nullptr, 0,
                     nullptr, nullptr, 0, nullptr, 0, nullptr, nullptr, nullptr,
                     wtwho, BB, K2H, 0, nullptr, 0, sA, sW, blockIdx.x, 128);
        } else if (blockIdx.x == 128) {
            const int lane = threadIdx.x & 31, wid = threadIdx.x >> 5;
            for (int r = wid; r < BB; r += 4) {
                float s = 0.f;
                for (int h = lane; h < HH; h += 32)
                    s += htout[(size_t)r * K2H + h] * p.reg_w[h];
#pragma unroll
                for (int o = 16; o; o >>= 1) s += __shfl_xor_sync(0xffffffffu, s, o);
                if (lane == 0) {
                    const float tv = s + p.reg_b[0];
                    p.out[r * LOOKN + k] = tv;
                    lab[r] = tv;
                }
            }
        } else {
            const int base = (blockIdx.x - 129) * NTHR + threadIdx.x;
            for (int i = base; i < BB * K2H; i += (NBLK - 129) * NTHR) {
                he0[i] = 0.f;
                hm0[i] = 0.f;
            }
        }
        gsync(++ph);

        for (int l = 0; l < LEN; l++) {
            float* hein  = (l & 1) ? he1 : he0;
            float* heout = (l & 1) ? he0 : he1;
            float* hmin  = (l & 1) ? hm1 : hm0;
            float* hmout = (l & 1) ? hm0 : hm1;

            // tu = tanh(hein@We^T + wi_x[l] + wt)
            gemm_mma(hein, K2H, WE32, K2H, nullptr, 0, nullptr, 0,
                     nullptr, wiseq + (size_t)l * HH, LEN*HH, wtwho, K2H,
                     nullptr, nullptr, nullptr,
                     tu, BB, HH, 1, nullptr, 0, sA, sW, blockIdx.x, NBLK);
            gsync(++ph);
            // sc = tu @ Vd^T + Vd_b
            gemm_mma(tu, 512, VD32, 512, nullptr, 0, nullptr, 0,
                     p.Vd_b, nullptr, 0, nullptr, 0, nullptr, nullptr, nullptr,
                     sc, BB, HH, 0, nullptr, 0, sA, sW, blockIdx.x, NBLK);
            gsync(++ph);
            if (blockIdx.x < BB) softmax_dev(sc, p.inp, l, xm, red);
            gsync(++ph);
            // sp gates (fused LSTM)
            gemm_mma(xm, 512, SPIH, 512, hein, K2H, SPHH, 512,
                     bspi, nullptr, 0, nullptr, 0, nullptr, nullptr, hein,
                     heout, BB, H4, 2, nullptr, 0, sA, sW, blockIdx.x, NBLK);
            gsync(++ph);
            // mid gates (fused LSTM) + mid2 output
            gemm_mma(heout, K2H, MDIH, 512, hmin, K2H, MDHH, 512,
                     bmdi, nullptr, 0, nullptr, 0, nullptr, nullptr, hmin,
                     hmout, BB, H4, 2, mid2 + (size_t)l * HH, LEN*HH,
                     sA, sW, blockIdx.x, NBLK);
            gsync(++ph);
        }
        // y = mid2 @ Wx^T + Wx_b
        gemm_mma(mid2, 512, WX32, 512, nullptr, 0, nullptr, 0,
                 p.Wx_b, nullptr, 0, nullptr, 0, nullptr, nullptr, nullptr,
                 ybuf, BB*LEN, HH, 0, nullptr, 0, sA, sW, blockIdx.x, NBLK);
        gsync(++ph);
        if (blockIdx.x < BB) dec_dev(ybuf, wtwho + 512, p.V_w, p.V_b, mid2, decin, ssc);
        gsync(++ph);
    }
}

// ---- prep: tf32 conversions, gate interleaving, bias combines ----
__global__ __launch_bounds__(256) void prep_k(
    const float* bihsp, const float* bhhsp, const float* bihtg, const float* bhhtg,
    const float* bihmid, const float* bhhmid, const float* wihtg,
    const float* wtw, const float* whw,
    const float* wisp, const float* whsp, const float* whtg,
    const float* wimd, const float* whmd,
    const float* wiw, const float* wew, const float* vdw, const float* wxw)
{
    const int nt = gridDim.x * 256;
    const int gid = blockIdx.x * 256 + threadIdx.x;
    uint32_t* WI32   = (uint32_t*)(g_buf + O_WI32);
    uint32_t* WE32   = (uint32_t*)(g_buf + O_WE32);
    uint32_t* VD32   = (uint32_t*)(g_buf + O_VD32);
    uint32_t* WX32   = (uint32_t*)(g_buf + O_WX32);
    uint32_t* WTWH32 = (uint32_t*)(g_buf + O_WTWH32);
    uint32_t* SPIH   = (uint32_t*)(g_buf + O_SPIH);
    uint32_t* SPHH   = (uint32_t*)(g_buf + O_SPHH);
    uint32_t* TGX    = (uint32_t*)(g_buf + O_TGX);
    uint32_t* TGHH   = (uint32_t*)(g_buf + O_TGHH);
    uint32_t* MDIH   = (uint32_t*)(g_buf + O_MDIH);
    uint32_t* MDHH   = (uint32_t*)(g_buf + O_MDHH);

    for (int i = gid; i < 512*512; i += nt) {
        WI32[i] = f2tf32(wiw[i]);
        VD32[i] = f2tf32(vdw[i]);
        WX32[i] = f2tf32(wxw[i]);
    }
    for (int i = gid; i < 512*1024; i += nt) WE32[i] = f2tf32(wew[i]);
    for (int i = gid; i < 1024*1024; i += nt) {
        const int r = i >> 10, c = i & 1023;
        WTWH32[i] = f2tf32(r < 512 ? wtw[(size_t)r*1024 + c]
                                   : whw[(size_t)(r-512)*1024 + c]);
    }
    for (int i = gid; i < H4*512; i += nt) {
        const int rp = i >> 9, kk = i & 511;
        const int h = rp >> 2, gg = rp & 3;
        const size_t src = (size_t)(gg * 512 + h);
        SPIH[i] = f2tf32(wisp[src*512 + kk]);
        SPHH[i] = f2tf32(whsp[src*512 + kk]);
        TGHH[i] = f2tf32(whtg[src*512 + kk]);
        MDIH[i] = f2tf32(wimd[src*512 + kk]);
        MDHH[i] = f2tf32(whmd[src*512 + kk]);
        TGX[i]  = f2tf32(wihtg[src*513 + 1 + kk]);
    }
    for (int i = gid; i < H4; i += nt) {
        const int h = i >> 2, gg = i & 3;
        const int s = gg * 512 + h;
        g_buf[O_BSPI + i]  = bihsp[s] + bhhsp[s];
        g_buf[O_BTGI + i]  = bihtg[s] + bhhtg[s];
        g_buf[O_BMDI + i]  = bihmid[s] + bhhmid[s];
        g_buf[O_WTGCI + i] = wihtg[(size_t)s * 513];
    }
}

__global__ __launch_bounds__(256) void init_k(const float* __restrict__ labp)
{
    const int i = blockIdx.x * 256 + threadIdx.x;
    if (i < NSUB) g_arr[i * 32] = 0u;
    if (i == NSUB) g_master = 0u;
    if (i == NSUB + 1) g_rel = 0u;
    if (i < BB * K2H) g_buf[O_HT0 + i] = 0.f;
    if (i < BB * HH)  g_buf[O_DECIN + i] = 0.f;
    if (i < BB)       g_buf[O_LAB + i] = labp[(size_t)i * LABW + STARTI];
}

extern "C" void kernel_launch(void* const* d_in, const int* in_sizes, int n_in,
                              void* d_out, int out_size)
{
    Params p;
    p.inp   = (const float*)d_in[0];
    p.Wi_b  = (const float*)d_in[15];
    p.Vd_b  = (const float*)d_in[19];
    p.Wx_b  = (const float*)d_in[21];
    p.V_w   = (const float*)d_in[23];
    p.V_b   = (const float*)d_in[24];
    p.reg_w = (const float*)d_in[25];
    p.reg_b = (const float*)d_in[26];
    p.out   = (float*)d_out;

    float* gb = nullptr;
    cudaGetSymbolAddress((void**)&gb, g_buf);
    p.gb = gb;

    prep_k<<<2048, 256>>>(
        (const float*)d_in[4], (const float*)d_in[5], (const float*)d_in[8],
        (const float*)d_in[9], (const float*)d_in[12], (const float*)d_in[13],
        (const float*)d_in[6], (const float*)d_in[17], (const float*)d_in[22],
        (const float*)d_in[2], (const float*)d_in[3], (const float*)d_in[7],
        (const float*)d_in[10], (const float*)d_in[11],
        (const float*)d_in[14], (const float*)d_in[16],
        (const float*)d_in[18], (const float*)d_in[20]);
    init_k<<<(BB * K2H + 255) / 256, 256>>>((const float*)d_in[1]);
    mega<<<NBLK, NTHR>>>(p);
}